// round 1
// baseline (speedup 1.0000x reference)
#include <cuda_runtime.h>

// ============================================================================
// OHEM loss (CRAFT hard negative mining), single-data-pass histogram select.
//
// Per channel c in {character, affinity}:
//   loss_i = (pred_i - targ_i)^2
//   pos: targ >= 0.1  -> pos_cnt, pos_sum
//   neg: targ <= 0.0  -> 13-bit histogram of float bits of loss (non-negative
//        floats sort by bit pattern), with packed (count | fixed-point sum)
//   k = min(max(1000, 3*pos_cnt), neg_cnt)
//   neg_sum = exact sum of bins above threshold bin + r * mean(threshold bin)
//   loss_c = (pos_sum + neg_sum) / (pos_cnt + k)
// out = 2*loss_char + loss_aff
// ============================================================================

#define NBINS   8192
#define BSHIFT  19                  // 32 - 13 bits
#define FPSCALE 262144.0f           // 2^18 fixed-point scale for bin sums
#define INV_FPSCALE (1.0 / 262144.0)
#define SUMMASK ((1ULL << 40) - 1ULL)
#define CNTONE  (1ULL << 40)

__device__ unsigned long long g_hist[2 * NBINS];
__device__ unsigned long long g_pos_cnt[2];
__device__ double             g_pos_sum[2];

// ---------------------------------------------------------------------------
__global__ void ohem_zero_kernel() {
    int i = blockIdx.x * blockDim.x + threadIdx.x;
    if (i < 2 * NBINS) g_hist[i] = 0ULL;
    if (i < 2) { g_pos_cnt[i] = 0ULL; g_pos_sum[i] = 0.0; }
}

// ---------------------------------------------------------------------------
// Pass 1: fused read of output (float4 = 2 pixels x 2 channels) + both maps.
// Shared-memory privatized histograms: 2 channels x 8192 bins x 8B = 128 KB.
// ---------------------------------------------------------------------------
__global__ __launch_bounds__(1024, 1)
void ohem_pass1(const float4* __restrict__ out4,
                const float2* __restrict__ cm2,
                const float2* __restrict__ am2,
                int npairs)
{
    extern __shared__ unsigned long long sh[];   // [2 * NBINS]
    for (int i = threadIdx.x; i < 2 * NBINS; i += 1024) sh[i] = 0ULL;
    __syncthreads();

    float    psum0 = 0.f, psum1 = 0.f;
    unsigned pcnt0 = 0,   pcnt1 = 0;

    const int stride = gridDim.x * 1024;
    for (int p = blockIdx.x * 1024 + threadIdx.x; p < npairs; p += stride) {
        float4 o  = __ldg(out4 + p);
        float2 cm = __ldg(cm2 + p);
        float2 am = __ldg(am2 + p);

        // pixel 0, channel 0
        {
            float d = o.x - cm.x; float l = d * d;
            if (cm.x >= 0.1f)      { pcnt0++; psum0 += l; }
            else if (cm.x <= 0.0f) {
                unsigned b = __float_as_uint(l) >> BSHIFT;
                atomicAdd(&sh[b], CNTONE | (unsigned long long)__float2uint_rn(l * FPSCALE));
            }
        }
        // pixel 0, channel 1
        {
            float d = o.y - am.x; float l = d * d;
            if (am.x >= 0.1f)      { pcnt1++; psum1 += l; }
            else if (am.x <= 0.0f) {
                unsigned b = __float_as_uint(l) >> BSHIFT;
                atomicAdd(&sh[NBINS + b], CNTONE | (unsigned long long)__float2uint_rn(l * FPSCALE));
            }
        }
        // pixel 1, channel 0
        {
            float d = o.z - cm.y; float l = d * d;
            if (cm.y >= 0.1f)      { pcnt0++; psum0 += l; }
            else if (cm.y <= 0.0f) {
                unsigned b = __float_as_uint(l) >> BSHIFT;
                atomicAdd(&sh[b], CNTONE | (unsigned long long)__float2uint_rn(l * FPSCALE));
            }
        }
        // pixel 1, channel 1
        {
            float d = o.w - am.y; float l = d * d;
            if (am.y >= 0.1f)      { pcnt1++; psum1 += l; }
            else if (am.y <= 0.0f) {
                unsigned b = __float_as_uint(l) >> BSHIFT;
                atomicAdd(&sh[NBINS + b], CNTONE | (unsigned long long)__float2uint_rn(l * FPSCALE));
            }
        }
    }
    __syncthreads();

    // Flush shared histograms to global (spread-address atomics).
    for (int i = threadIdx.x; i < 2 * NBINS; i += 1024) {
        unsigned long long v = sh[i];
        if (v) atomicAdd(&g_hist[i], v);
    }

    // Block-reduce positive stats.
    const unsigned mask = 0xffffffffu;
    for (int off = 16; off; off >>= 1) {
        psum0 += __shfl_down_sync(mask, psum0, off);
        psum1 += __shfl_down_sync(mask, psum1, off);
        pcnt0 += __shfl_down_sync(mask, pcnt0, off);
        pcnt1 += __shfl_down_sync(mask, pcnt1, off);
    }
    __shared__ float    rs0[32], rs1[32];
    __shared__ unsigned rc0[32], rc1[32];
    int w = threadIdx.x >> 5, lane = threadIdx.x & 31;
    if (lane == 0) { rs0[w] = psum0; rs1[w] = psum1; rc0[w] = pcnt0; rc1[w] = pcnt1; }
    __syncthreads();
    if (w == 0) {
        float    a0 = rs0[lane], a1 = rs1[lane];
        unsigned c0 = rc0[lane], c1 = rc1[lane];
        for (int off = 16; off; off >>= 1) {
            a0 += __shfl_down_sync(mask, a0, off);
            a1 += __shfl_down_sync(mask, a1, off);
            c0 += __shfl_down_sync(mask, c0, off);
            c1 += __shfl_down_sync(mask, c1, off);
        }
        if (lane == 0) {
            atomicAdd(&g_pos_sum[0], (double)a0);
            atomicAdd(&g_pos_sum[1], (double)a1);
            atomicAdd(&g_pos_cnt[0], (unsigned long long)c0);
            atomicAdd(&g_pos_cnt[1], (unsigned long long)c1);
        }
    }
}

// ---------------------------------------------------------------------------
// Finalize: single block suffix-scans each channel's 8192-bin histogram,
// finds the k-th-largest threshold bin, assembles neg_sum, writes the scalar.
// ---------------------------------------------------------------------------
__global__ __launch_bounds__(1024, 1)
void ohem_finalize(float* __restrict__ out)
{
    __shared__ unsigned  sc[1024];
    __shared__ double    ss[1024];
    __shared__ double    s_negsum[2];
    __shared__ long long s_k[2];

    const int t = threadIdx.x;

    for (int c = 0; c < 2; c++) {
        // Load my 8 bins, decode packed count/sum.
        unsigned cnt[8];
        double   sum[8];
        unsigned tc = 0; double ts = 0.0;
        #pragma unroll
        for (int j = 0; j < 8; j++) {
            unsigned long long v = g_hist[c * NBINS + t * 8 + j];
            cnt[j] = (unsigned)(v >> 40);
            sum[j] = (double)(v & SUMMASK) * INV_FPSCALE;
            tc += cnt[j]; ts += sum[j];
        }
        sc[t] = tc; ss[t] = ts;
        __syncthreads();

        // Inclusive suffix scan over 1024 per-thread totals (Hillis-Steele).
        for (int off = 1; off < 1024; off <<= 1) {
            unsigned a  = sc[t];
            double   b  = ss[t];
            unsigned a2 = (t + off < 1024) ? sc[t + off] : 0u;
            double   b2 = (t + off < 1024) ? ss[t + off] : 0.0;
            __syncthreads();
            sc[t] = a + a2; ss[t] = b + b2;
            __syncthreads();
        }

        long long num_neg = (long long)sc[0];
        long long num_pos = (long long)g_pos_cnt[c];
        long long k = 3 * num_pos;
        if (k < 1000)    k = 1000;
        if (k > num_neg) k = num_neg;

        unsigned SN  = (t < 1023) ? sc[t + 1] : 0u;     // suffix count above my range
        double   SNs = (t < 1023) ? ss[t + 1] : 0.0;    // suffix sum above my range
        if (t == 0) { s_negsum[c] = 0.0; s_k[c] = k; }
        __syncthreads();

        // Walk my 8 bins top-down; exactly one thread crosses the k boundary.
        if (k > 0) {
            long long cum  = (long long)SN;
            double    cumS = SNs;
            #pragma unroll
            for (int j = 7; j >= 0; j--) {
                long long c2 = cum + (long long)cnt[j];
                if (cum < k && k <= c2) {
                    long long r   = k - cum;
                    double    mean = (cnt[j] > 0) ? (sum[j] / (double)cnt[j]) : 0.0;
                    s_negsum[c] = cumS + (double)r * mean;
                }
                cum  = c2;
                cumS += sum[j];
            }
        }
        __syncthreads();
    }

    if (t == 0) {
        double l0 = (g_pos_sum[0] + s_negsum[0]) / (double)(g_pos_cnt[0] + (unsigned long long)s_k[0]);
        double l1 = (g_pos_sum[1] + s_negsum[1]) / (double)(g_pos_cnt[1] + (unsigned long long)s_k[1]);
        out[0] = (float)(2.0 * l0 + l1);
    }
}

// ---------------------------------------------------------------------------
extern "C" void kernel_launch(void* const* d_in, const int* in_sizes, int n_in,
                              void* d_out, int out_size)
{
    const float* output = (const float*)d_in[0];   // [B,H,W,2]
    const float* cm     = (const float*)d_in[1];   // [B,H,W]
    const float* am     = (const float*)d_in[2];   // [B,H,W]
    const int n      = in_sizes[1];                // B*H*W
    const int npairs = n / 2;

    cudaFuncSetAttribute(ohem_pass1,
                         cudaFuncAttributeMaxDynamicSharedMemorySize,
                         2 * NBINS * (int)sizeof(unsigned long long));

    ohem_zero_kernel<<<(2 * NBINS + 255) / 256, 256>>>();
    ohem_pass1<<<148, 1024, 2 * NBINS * sizeof(unsigned long long)>>>(
        (const float4*)output, (const float2*)cm, (const float2*)am, npairs);
    ohem_finalize<<<1, 1024>>>((float*)d_out);
}